// round 12
// baseline (speedup 1.0000x reference)
#include <cuda_runtime.h>
#include <cuda_bf16.h>
#include <cub/cub.cuh>
#include <cstdint>

// ---------------------------------------------------------------------------
// FlattenedWindowMapping: flat2win (Np), win2flat (N), then 6 stable argsorts
// of int64 hash keys (vx,vy,vz for shifted in {false,true}).
//
// DATA MODEL (pinned in round 10 from the full failure history):
//   coords: int32, in_sizes[0] = 4N   (harness lowers int64 -> int32)
//   d_out : float32, out_size = Np+7N (harness compares outputs in float32;
//           all values < 2^24 so float32 is exact)
// A size-arithmetic dispatcher keeps the int64-bitcast variants as fallbacks,
// and bid is clamped so a wrong model yields rel_err evidence, never a trap.
//
// Stable-argsort trick: hash keys fit in 33 bits after bias; pack
//   composite = (key + BIAS) << 21 | original_index   (54 bits total)
// -> all composites unique, ascending radix sort == stable argsort,
//    answer = low 21 bits.
// ---------------------------------------------------------------------------

static constexpr long long NMAX      = 2097152;        // 2^21 > 1,986,000
static constexpr long long BIAS      = 1LL << 22;      // covers min key ~ -1.79M
static constexpr int       IDX_BITS  = 21;
static constexpr unsigned long long IDX_MASK = (1ull << IDX_BITS) - 1ull;
static constexpr size_t    TEMP_BYTES = 64ull * 1024 * 1024;

__device__ __align__(256) unsigned long long g_keys[6 * NMAX];    // ~100.7 MB
__device__ __align__(256) unsigned long long g_sorted[6 * NMAX];  // ~100.7 MB
__device__ __align__(256) unsigned long long g_temp[TEMP_BYTES / 8];

struct Meta {
    long long bsp[5];    // padded batch prefix
    long long diff[4];   // bsp[b] - bs[b]
    long long r[4];      // count % 128
};
__device__ Meta g_meta;

// --- 1. batch boundaries via binary search (bids are sorted) + metadata ----
template<bool IN64>
__global__ void setup_kernel(const void* __restrict__ coordsRaw, long long N)
{
    __shared__ long long bnd[3];
    int t = threadIdx.x;
    if (t < 3) {
        long long k = t + 1, lo = 0, hi = N;
        while (lo < hi) {
            long long mid = (lo + hi) >> 1;
            long long b = IN64 ? ((const long long*)coordsRaw)[4 * mid]
                               : (long long)((const int*)coordsRaw)[4 * mid];
            if (b < k) lo = mid + 1; else hi = mid;
        }
        bnd[t] = lo;
    }
    __syncthreads();
    if (t == 0) {
        long long bs[5] = {0, bnd[0], bnd[1], bnd[2], N};
        long long acc = 0;
        g_meta.bsp[0] = 0;
        for (int j = 0; j < 4; j++) {
            long long cnt  = bs[j + 1] - bs[j];
            long long cntp = (cnt + 127) / 128 * 128;
            g_meta.diff[j] = acc - bs[j];          // bsp[j] - bs[j]
            acc += cntp;
            g_meta.bsp[j + 1] = acc;
            g_meta.r[j] = cnt & 127;
        }
    }
}

// --- hash keys (exact port of reference _hash_keys, coords >= 0) -----------
// n2o=16, m2o=16, l2o=8 ; n1=m1=3*33=99, l1=3*9=27 ; n2=m2=48, l2=24
// n2*m2*l2 = m2*l2*n2 = l2*n2*m2 = 55296
__device__ __forceinline__ void hash3(long long x, long long y, long long z,
                                      long long boff,
                                      long long& vx, long long& vy, long long& vz)
{
    long long x1 = x >> 4, y1 = y >> 4, z1 = z >> 3;
    long long x2 = x & 15, y2 = y & 15, z2 = z & 7;
    long long sx  = 1 - 2 * (x1 & 1), sy  = 1 - 2 * (y1 & 1), sz  = 1 - 2 * (z1 & 1);
    long long s2x = 1 - 2 * (x2 & 1), s2y = 1 - 2 * (y2 & 1), s2z = 1 - 2 * (z2 & 1);
    vx = (99 * y1 + 9801 * z1 + sy * x1) * 55296
       + sy * (48 * x2 + 2304 * z2 + s2x * y2) + boff;
    vy = (99 * z1 + 2673 * x1 + sz * y1) * 55296
       + sz * (24 * y2 + 1152 * x2 + s2y * z2) + boff;
    vz = (27 * x1 + 2673 * y1 + sx * z1) * 55296
       + sx * (48 * z2 + 1152 * y2 + s2z * x2) + boff;
}

__device__ __forceinline__ unsigned long long pack(long long v, unsigned idx)
{
    return ((unsigned long long)(v + BIAS) << IDX_BITS) | (unsigned long long)idx;
}

// --- 2. one pass over coords: 6 composite key arrays + win2flat ------------
template<bool IN64, bool OUT64>
__global__ void keygen_kernel(const void* __restrict__ coordsRaw, int N,
                              unsigned long long* __restrict__ keys,
                              void* __restrict__ win2flat)
{
    int i = blockIdx.x * blockDim.x + threadIdx.x;
    if (i >= N) return;
    long long bid, x, y, z;
    if (IN64) {
        longlong4 c = ((const longlong4*)coordsRaw)[i];   // 2x LDG.128
        bid = c.x; x = c.y; y = c.z; z = c.w;
    } else {
        int4 c = ((const int4*)coordsRaw)[i];             // 1x LDG.128
        bid = c.x; x = c.y; y = c.z; z = c.w;
    }
    int b4 = (int)bid & 3;                                // never trap on model error

    long long w = (long long)i + g_meta.diff[b4];
    if (OUT64) ((long long*)win2flat)[i] = w;
    else       ((float*)win2flat)[i]     = (float)w;      // exact: < 2^24

    long long boff = (long long)b4 * 167772160LL;         // bid * n*m*l*10
    long long vx, vy, vz;
    hash3(x, y, z, boff, vx, vy, vz);
    keys[0 * NMAX + i] = pack(vx, i);
    keys[1 * NMAX + i] = pack(vy, i);
    keys[2 * NMAX + i] = pack(vz, i);
    hash3(x + 8, y + 8, z + 4, boff, vx, vy, vz);         // shifted by window/2
    keys[3 * NMAX + i] = pack(vx, i);
    keys[4 * NMAX + i] = pack(vy, i);
    keys[5 * NMAX + i] = pack(vz, i);
}

// --- 3. flat2win over padded index space -----------------------------------
template<bool OUT64>
__global__ void flat2win_kernel(void* __restrict__ outRaw, long long Np)
{
    long long p = (long long)blockIdx.x * blockDim.x + threadIdx.x;
    if (p >= Np) return;
    int b = 0;
    if (p >= g_meta.bsp[1]) b = 1;
    if (p >= g_meta.bsp[2]) b = 2;
    if (p >= g_meta.bsp[3]) b = 3;
    long long r = g_meta.r[b];
    bool pad = (r != 0) && (p >= g_meta.bsp[b + 1] - 128 + r);
    long long v = p - (pad ? 128LL : 0LL) - g_meta.diff[b];
    if (OUT64) ((long long*)outRaw)[p] = v;
    else       ((float*)outRaw)[p]     = (float)v;
}

// --- 4a. float path: composite -> float index ------------------------------
__global__ void extract_float_kernel(const unsigned long long* __restrict__ sorted,
                                     float* __restrict__ out, int N)
{
    int i = blockIdx.x * blockDim.x + threadIdx.x;
    if (i >= N) return;
    int s = blockIdx.y;
    unsigned idx = (unsigned)(sorted[(size_t)s * NMAX + i] & IDX_MASK);
    out[(size_t)s * N + i] = (float)idx;
}

// --- 4b. int64 path: strip key bits in place -------------------------------
__global__ void mask_kernel(unsigned long long* __restrict__ a, long long n)
{
    long long i = (long long)blockIdx.x * blockDim.x + threadIdx.x;
    if (i < n) a[i] &= IDX_MASK;
}

extern "C" void kernel_launch(void* const* d_in, const int* in_sizes, int n_in,
                              void* d_out, int out_size)
{
    const void* coords = d_in[0];
    long long S   = (long long)in_sizes[0];
    long long M32 = (long long)out_size;

    // --- size-arithmetic model dispatch ---
    // preferred: (k=4 int32 input, w=1 float32 output); fallbacks cover
    // int64-bitcast input (k=8) / output (w=2) and rows-count input (k=1).
    long long N = 0, Np = 0;
    bool in64 = false, out64 = false, found = false;
    const long long KS[3] = {4, 8, 1};
    for (int wi = 1; wi <= 2 && !found; wi++) {
        if (M32 % wi) continue;
        long long M = M32 / wi;
        for (int ki = 0; ki < 3 && !found; ki++) {
            long long k = KS[ki];
            if (S % k) continue;
            long long n  = S / k;
            long long np = M - 7 * n;
            if (n > 0 && n <= NMAX && np >= n && np < n + 512) {
                N = n; Np = np; in64 = (k == 8); out64 = (wi == 2); found = true;
            }
        }
    }
    if (!found) { N = S / 4; Np = M32 - 7 * N; in64 = false; out64 = false; }
    if (N <= 0 || Np <= 0) return;

    void *keysPtr = nullptr, *sortedPtr = nullptr, *tempPtr = nullptr;
    cudaGetSymbolAddress(&keysPtr, g_keys);
    cudaGetSymbolAddress(&sortedPtr, g_sorted);
    cudaGetSymbolAddress(&tempPtr, g_temp);
    unsigned long long* keys = (unsigned long long*)keysPtr;

    int nbN  = (int)((N + 255) / 256);
    int nbNp = (int)((Np + 255) / 256);

    if (in64) setup_kernel<true ><<<1, 32>>>(coords, N);
    else      setup_kernel<false><<<1, 32>>>(coords, N);

    if (out64) {
        long long* out = (long long*)d_out;
        if (in64) keygen_kernel<true , true><<<nbN, 256>>>(coords, (int)N, keys, out + Np);
        else      keygen_kernel<false, true><<<nbN, 256>>>(coords, (int)N, keys, out + Np);
        flat2win_kernel<true><<<nbNp, 256>>>(out, Np);

        unsigned long long* sortedBase = (unsigned long long*)(out + Np + N);
        for (int s = 0; s < 6; s++) {
            size_t tbs = TEMP_BYTES;
            cub::DeviceRadixSort::SortKeys(tempPtr, tbs,
                                           keys + (size_t)s * NMAX,
                                           sortedBase + (size_t)s * N,
                                           (int)N, 0, 33 + IDX_BITS);
        }
        long long total = 6 * N;
        mask_kernel<<<(int)((total + 255) / 256), 256>>>(sortedBase, total);
    } else {
        float* out = (float*)d_out;
        if (in64) keygen_kernel<true , false><<<nbN, 256>>>(coords, (int)N, keys, out + Np);
        else      keygen_kernel<false, false><<<nbN, 256>>>(coords, (int)N, keys, out + Np);
        flat2win_kernel<false><<<nbNp, 256>>>(out, Np);

        unsigned long long* sorted = (unsigned long long*)sortedPtr;
        for (int s = 0; s < 6; s++) {
            size_t tbs = TEMP_BYTES;
            cub::DeviceRadixSort::SortKeys(tempPtr, tbs,
                                           keys   + (size_t)s * NMAX,
                                           sorted + (size_t)s * NMAX,
                                           (int)N, 0, 33 + IDX_BITS);
        }
        dim3 eg((unsigned)nbN, 6);
        extract_float_kernel<<<eg, 256>>>(sorted, out + Np + N, (int)N);
    }
}

// round 16
// speedup vs baseline: 1.7226x; 1.7226x over previous
#include <cuda_runtime.h>
#include <cuda_bf16.h>
#include <cub/cub.cuh>
#include <cstdint>

// ---------------------------------------------------------------------------
// FlattenedWindowMapping: flat2win (Np), win2flat (N), then 6 stable argsorts
// of int64 hash keys (vx,vy,vz for shifted in {false,true}).
//
// DATA MODEL (confirmed PASSING round 12): coords = int32 (in_sizes[0]=4N),
// d_out = float32 (out_size = Np+7N; all values < 2^24 so float32 exact).
// Size-arithmetic dispatcher retains int64-bitcast fallbacks.
//
// SORT (round 13 design, fixed round 15): ONE batched stable radix sort.
//   composite = seg(3 bits) << 54 | (key + BIAS)(33 bits) << 21 | idx(21 bits)
// CUB radix sort is stable and keygen emits composites in idx order, so the
// idx bits never need sorting: sort bits [21,57) -> 5 onesweep passes over
// 6N = 11.9M elements. Segment-major result == output layout.
//
// R15 FIX: TEMP_BYTES 64MB -> 192MB. CUB's temp blob holds the alternate key
// buffer (6N * 8B = 95.3MB); undersized temp makes CUB return invalid
// argument WITHOUT launching, which poisons graph capture (the R13/R14
// failure at harness:367).
// ---------------------------------------------------------------------------

static constexpr long long NMAX      = 2097152;        // 2^21 > 1,986,000
static constexpr long long BIAS      = 1LL << 22;      // covers min key ~ -1.79M
static constexpr int       IDX_BITS  = 21;
static constexpr int       SEG_SHIFT = 54;             // 21 idx + 33 key bits
static constexpr int       END_BIT   = 57;             // 3 segment bits
static constexpr unsigned long long IDX_MASK = (1ull << IDX_BITS) - 1ull;
static constexpr size_t    TEMP_BYTES = 192ull * 1024 * 1024;

__device__ __align__(256) unsigned long long g_keys[6 * NMAX];    // ~100.7 MB
__device__ __align__(256) unsigned long long g_sorted[6 * NMAX];  // ~100.7 MB
__device__ __align__(256) unsigned long long g_temp[TEMP_BYTES / 8];

struct Meta {
    long long bsp[5];    // padded batch prefix
    long long diff[4];   // bsp[b] - bs[b]
    long long r[4];      // count % 128
};
__device__ Meta g_meta;

// --- 1. batch boundaries via binary search (bids are sorted) + metadata ----
template<bool IN64>
__global__ void setup_kernel(const void* __restrict__ coordsRaw, long long N)
{
    __shared__ long long bnd[3];
    int t = threadIdx.x;
    if (t < 3) {
        long long k = t + 1, lo = 0, hi = N;
        while (lo < hi) {
            long long mid = (lo + hi) >> 1;
            long long b = IN64 ? ((const long long*)coordsRaw)[4 * mid]
                               : (long long)((const int*)coordsRaw)[4 * mid];
            if (b < k) lo = mid + 1; else hi = mid;
        }
        bnd[t] = lo;
    }
    __syncthreads();
    if (t == 0) {
        long long bs[5] = {0, bnd[0], bnd[1], bnd[2], N};
        long long acc = 0;
        g_meta.bsp[0] = 0;
        for (int j = 0; j < 4; j++) {
            long long cnt  = bs[j + 1] - bs[j];
            long long cntp = (cnt + 127) / 128 * 128;
            g_meta.diff[j] = acc - bs[j];          // bsp[j] - bs[j]
            acc += cntp;
            g_meta.bsp[j + 1] = acc;
            g_meta.r[j] = cnt & 127;
        }
    }
}

// --- hash keys (exact port of reference _hash_keys, coords >= 0) -----------
// n2o=16, m2o=16, l2o=8 ; n1=m1=3*33=99, l1=3*9=27 ; n2=m2=48, l2=24
// n2*m2*l2 = m2*l2*n2 = l2*n2*m2 = 55296
__device__ __forceinline__ void hash3(long long x, long long y, long long z,
                                      long long boff,
                                      long long& vx, long long& vy, long long& vz)
{
    long long x1 = x >> 4, y1 = y >> 4, z1 = z >> 3;
    long long x2 = x & 15, y2 = y & 15, z2 = z & 7;
    long long sx  = 1 - 2 * (x1 & 1), sy  = 1 - 2 * (y1 & 1), sz  = 1 - 2 * (z1 & 1);
    long long s2x = 1 - 2 * (x2 & 1), s2y = 1 - 2 * (y2 & 1), s2z = 1 - 2 * (z2 & 1);
    vx = (99 * y1 + 9801 * z1 + sy * x1) * 55296
       + sy * (48 * x2 + 2304 * z2 + s2x * y2) + boff;
    vy = (99 * z1 + 2673 * x1 + sz * y1) * 55296
       + sz * (24 * y2 + 1152 * x2 + s2y * z2) + boff;
    vz = (27 * x1 + 2673 * y1 + sx * z1) * 55296
       + sx * (48 * z2 + 1152 * y2 + s2z * x2) + boff;
}

template<int SEG>
__device__ __forceinline__ unsigned long long pack(long long v, unsigned idx)
{
    return ((unsigned long long)SEG << SEG_SHIFT)
         | ((unsigned long long)(v + BIAS) << IDX_BITS)
         | (unsigned long long)idx;
}

// --- 2. one pass over coords: 6 segment-tagged key arrays + win2flat -------
template<bool IN64, bool OUT64>
__global__ void keygen_kernel(const void* __restrict__ coordsRaw, int N,
                              unsigned long long* __restrict__ keys,
                              void* __restrict__ win2flat)
{
    int i = blockIdx.x * blockDim.x + threadIdx.x;
    if (i >= N) return;
    long long bid, x, y, z;
    if (IN64) {
        longlong4 c = ((const longlong4*)coordsRaw)[i];   // 2x LDG.128
        bid = c.x; x = c.y; y = c.z; z = c.w;
    } else {
        int4 c = ((const int4*)coordsRaw)[i];             // 1x LDG.128
        bid = c.x; x = c.y; y = c.z; z = c.w;
    }
    int b4 = (int)bid & 3;                                // never trap on model error

    long long w = (long long)i + g_meta.diff[b4];
    if (OUT64) ((long long*)win2flat)[i] = w;
    else       ((float*)win2flat)[i]     = (float)w;      // exact: < 2^24

    long long boff = (long long)b4 * 167772160LL;         // bid * n*m*l*10
    long long vx, vy, vz;
    hash3(x, y, z, boff, vx, vy, vz);
    keys[(size_t)0 * N + i] = pack<0>(vx, i);
    keys[(size_t)1 * N + i] = pack<1>(vy, i);
    keys[(size_t)2 * N + i] = pack<2>(vz, i);
    hash3(x + 8, y + 8, z + 4, boff, vx, vy, vz);         // shifted by window/2
    keys[(size_t)3 * N + i] = pack<3>(vx, i);
    keys[(size_t)4 * N + i] = pack<4>(vy, i);
    keys[(size_t)5 * N + i] = pack<5>(vz, i);
}

// --- 3. flat2win over padded index space -----------------------------------
template<bool OUT64>
__global__ void flat2win_kernel(void* __restrict__ outRaw, long long Np)
{
    long long p = (long long)blockIdx.x * blockDim.x + threadIdx.x;
    if (p >= Np) return;
    int b = 0;
    if (p >= g_meta.bsp[1]) b = 1;
    if (p >= g_meta.bsp[2]) b = 2;
    if (p >= g_meta.bsp[3]) b = 3;
    long long r = g_meta.r[b];
    bool pad = (r != 0) && (p >= g_meta.bsp[b + 1] - 128 + r);
    long long v = p - (pad ? 128LL : 0LL) - g_meta.diff[b];
    if (OUT64) ((long long*)outRaw)[p] = v;
    else       ((float*)outRaw)[p]     = (float)v;
}

// --- 4. composite -> index over the whole batched result -------------------
template<bool OUT64>
__global__ void extract_kernel(const unsigned long long* __restrict__ sorted,
                               void* __restrict__ outRaw, long long total)
{
    long long j = (long long)blockIdx.x * blockDim.x + threadIdx.x;
    if (j >= total) return;
    unsigned idx = (unsigned)(sorted[j] & IDX_MASK);
    if (OUT64) ((long long*)outRaw)[j] = (long long)idx;
    else       ((float*)outRaw)[j]     = (float)idx;
}

extern "C" void kernel_launch(void* const* d_in, const int* in_sizes, int n_in,
                              void* d_out, int out_size)
{
    const void* coords = d_in[0];
    long long S   = (long long)in_sizes[0];
    long long M32 = (long long)out_size;

    // --- size-arithmetic model dispatch (preferred: int32 in, float32 out) --
    long long N = 0, Np = 0;
    bool in64 = false, out64 = false, found = false;
    const long long KS[3] = {4, 8, 1};
    for (int wi = 1; wi <= 2 && !found; wi++) {
        if (M32 % wi) continue;
        long long M = M32 / wi;
        for (int ki = 0; ki < 3 && !found; ki++) {
            long long k = KS[ki];
            if (S % k) continue;
            long long n  = S / k;
            long long np = M - 7 * n;
            if (n > 0 && n <= NMAX && np >= n && np < n + 512) {
                N = n; Np = np; in64 = (k == 8); out64 = (wi == 2); found = true;
            }
        }
    }
    if (!found) { N = S / 4; Np = M32 - 7 * N; in64 = false; out64 = false; }
    if (N <= 0 || Np <= 0) return;

    void *keysPtr = nullptr, *sortedPtr = nullptr, *tempPtr = nullptr;
    cudaGetSymbolAddress(&keysPtr, g_keys);
    cudaGetSymbolAddress(&sortedPtr, g_sorted);
    cudaGetSymbolAddress(&tempPtr, g_temp);
    unsigned long long* keys   = (unsigned long long*)keysPtr;
    unsigned long long* sorted = (unsigned long long*)sortedPtr;

    int nbN  = (int)((N + 255) / 256);
    int nbNp = (int)((Np + 255) / 256);

    if (in64) setup_kernel<true ><<<1, 32>>>(coords, N);
    else      setup_kernel<false><<<1, 32>>>(coords, N);

    if (in64) {
        if (out64) keygen_kernel<true , true ><<<nbN, 256>>>(coords, (int)N, keys, (long long*)d_out + Np);
        else       keygen_kernel<true , false><<<nbN, 256>>>(coords, (int)N, keys, (float*)d_out + Np);
    } else {
        if (out64) keygen_kernel<false, true ><<<nbN, 256>>>(coords, (int)N, keys, (long long*)d_out + Np);
        else       keygen_kernel<false, false><<<nbN, 256>>>(coords, (int)N, keys, (float*)d_out + Np);
    }

    if (out64) flat2win_kernel<true ><<<nbNp, 256>>>(d_out, Np);
    else       flat2win_kernel<false><<<nbNp, 256>>>(d_out, Np);

    // ONE batched stable radix sort over all 6 segments, key bits only.
    // Stability of radix sort + idx-ordered input makes the low 21 bits
    // redundant for ordering: begin_bit = IDX_BITS.
    long long total = 6 * N;
    {
        size_t tbs = TEMP_BYTES;   // 192MB: alt key buffer (95.3MB) + overhead
        cub::DeviceRadixSort::SortKeys(tempPtr, tbs,
                                       keys, sorted, (int)total,
                                       IDX_BITS, END_BIT);
    }

    // indices -> output (segment-major == output layout)
    int nbT = (int)((total + 255) / 256);
    if (out64) extract_kernel<true ><<<nbT, 256>>>(sorted, (long long*)d_out + Np + N, total);
    else       extract_kernel<false><<<nbT, 256>>>(sorted, (float*)d_out + Np + N, total);
}